// round 1
// baseline (speedup 1.0000x reference)
#include <cuda_runtime.h>
#include <cuda_bf16.h>

#define NN 50000
#define EE 800000
#define RR 2
#define DD 128
#define GG 64
#define CC 8

// ---------------- scratch (static __device__ allocations; no cudaMalloc) ----
__device__ float g_h[NN * DD];          // feature ping buffer (gemm output)
__device__ float g_z[RR][NN * DD];      // per-relation aggregated features
__device__ float g_inv[RR][NN];         // inv sqrt degree (incl. self loop)
__device__ int   g_deg[RR][NN];         // in-degree (no self loop)
__device__ int   g_rowptr[RR][NN + 1];  // CSR row pointers by dst
__device__ int   g_fill[RR][NN];        // fill cursors
__device__ int   g_col[RR][EE];         // src node per CSR slot
__device__ float g_norm[RR][EE];        // inv[src]*inv[dst] per CSR slot

// ---------------- CSR construction ------------------------------------------
__global__ void zero_deg_kernel() {
    int idx = blockIdx.x * blockDim.x + threadIdx.x;
    if (idx < RR * NN) ((int*)g_deg)[idx] = 0;
}

__global__ void count_deg_kernel(const int* __restrict__ ei) {
    int idx = blockIdx.x * blockDim.x + threadIdx.x;
    if (idx >= RR * EE) return;
    int r = idx / EE, e = idx % EE;
    int dst = ei[r * 2 * EE + EE + e];
    atomicAdd(&g_deg[r][dst], 1);
}

__global__ void inv_sqrt_kernel() {
    int idx = blockIdx.x * blockDim.x + threadIdx.x;
    if (idx >= RR * NN) return;
    int r = idx / NN, i = idx % NN;
    g_inv[r][i] = rsqrtf((float)g_deg[r][i] + 1.0f);
}

// One block per relation; chunked Hillis-Steele inclusive scan of degrees.
__global__ void scan_kernel() {
    int r = blockIdx.x;
    __shared__ int sh[1024];
    __shared__ int s_carry;
    int t = threadIdx.x;
    if (t == 0) { s_carry = 0; g_rowptr[r][0] = 0; }
    __syncthreads();
    for (int base = 0; base < NN; base += 1024) {
        int idx = base + t;
        int v = (idx < NN) ? g_deg[r][idx] : 0;
        sh[t] = v;
        __syncthreads();
        #pragma unroll
        for (int off = 1; off < 1024; off <<= 1) {
            int add = (t >= off) ? sh[t - off] : 0;
            __syncthreads();
            sh[t] += add;
            __syncthreads();
        }
        int inc = sh[t] + s_carry;
        if (idx < NN) {
            g_rowptr[r][idx + 1] = inc;
            g_fill[r][idx] = inc - v;   // exclusive prefix = start slot
        }
        __syncthreads();
        if (t == 1023) s_carry = inc;
        __syncthreads();
    }
}

__global__ void fill_csr_kernel(const int* __restrict__ ei) {
    int idx = blockIdx.x * blockDim.x + threadIdx.x;
    if (idx >= RR * EE) return;
    int r = idx / EE, e = idx % EE;
    int src = ei[r * 2 * EE + e];
    int dst = ei[r * 2 * EE + EE + e];
    int pos = atomicAdd(&g_fill[r][dst], 1);
    g_col[r][pos]  = src;
    g_norm[r][pos] = g_inv[r][src] * g_inv[r][dst];
}

// ---------------- aggregation: z_r = A_r_norm h + d^-1 h --------------------
// One warp per dst node; each lane owns 4 channels (float4).
__global__ __launch_bounds__(256) void agg_kernel(const float* __restrict__ h) {
    int r = blockIdx.y;
    int gw = (blockIdx.x * blockDim.x + threadIdx.x) >> 5;
    int lane = threadIdx.x & 31;
    if (gw >= NN) return;
    const float4* hv = (const float4*)h;
    float4 acc = make_float4(0.f, 0.f, 0.f, 0.f);
    int beg = g_rowptr[r][gw], end = g_rowptr[r][gw + 1];
    for (int e = beg; e < end; e++) {
        int s    = __ldg(&g_col[r][e]);
        float nm = __ldg(&g_norm[r][e]);
        float4 v = __ldg(&hv[s * 32 + lane]);
        acc.x = fmaf(nm, v.x, acc.x);
        acc.y = fmaf(nm, v.y, acc.y);
        acc.z = fmaf(nm, v.z, acc.z);
        acc.w = fmaf(nm, v.w, acc.w);
    }
    float iv = g_inv[r][gw];
    float self = iv * iv;
    float4 v = __ldg(&hv[gw * 32 + lane]);
    acc.x = fmaf(self, v.x, acc.x);
    acc.y = fmaf(self, v.y, acc.y);
    acc.z = fmaf(self, v.z, acc.z);
    acc.w = fmaf(self, v.w, acc.w);
    ((float4*)g_z[r])[gw * 32 + lane] = acc;
}

// ---------------- fused dual GEMM: out = z0 W0 + z1 W1 + (b0+b1), opt relu --
// Block tile 128x128, 256 threads, 8x8 register micro-tile, K-chunk = 8.
__global__ __launch_bounds__(256) void gemm_dual_kernel(
    const float* __restrict__ W0, const float* __restrict__ W1,
    const float* __restrict__ b0, const float* __restrict__ b1,
    float* __restrict__ out, int do_relu)
{
    __shared__ float As[8][128];
    __shared__ float Bs[8][128];
    int row0 = blockIdx.x * 128;
    int t = threadIdx.x;
    int tx = t & 15;      // col group
    int ty = t >> 4;      // row group
    float acc[8][8];
    #pragma unroll
    for (int i = 0; i < 8; i++)
        #pragma unroll
        for (int j = 0; j < 8; j++) acc[i][j] = 0.f;

    #pragma unroll
    for (int phase = 0; phase < 2; phase++) {
        const float* Z  = g_z[phase];
        const float* Wp = phase ? W1 : W0;
        for (int kc = 0; kc < 128; kc += 8) {
            {   // A tile: 128 rows x 8 k
                int m = t >> 1;
                int k4 = (t & 1) * 4;
                int gr = row0 + m;
                float4 v = make_float4(0.f, 0.f, 0.f, 0.f);
                if (gr < NN) v = *(const float4*)&Z[gr * 128 + kc + k4];
                As[k4 + 0][m] = v.x; As[k4 + 1][m] = v.y;
                As[k4 + 2][m] = v.z; As[k4 + 3][m] = v.w;
            }
            {   // B tile: 8 k x 128 cols
                int k  = t >> 5;
                int c4 = (t & 31) * 4;
                *(float4*)&Bs[k][c4] = *(const float4*)&Wp[(kc + k) * 128 + c4];
            }
            __syncthreads();
            #pragma unroll
            for (int kk = 0; kk < 8; kk++) {
                float4 a0 = *(float4*)&As[kk][ty * 8];
                float4 a1 = *(float4*)&As[kk][ty * 8 + 4];
                float4 bq0 = *(float4*)&Bs[kk][tx * 8];
                float4 bq1 = *(float4*)&Bs[kk][tx * 8 + 4];
                float a[8] = {a0.x, a0.y, a0.z, a0.w, a1.x, a1.y, a1.z, a1.w};
                float bb[8] = {bq0.x, bq0.y, bq0.z, bq0.w, bq1.x, bq1.y, bq1.z, bq1.w};
                #pragma unroll
                for (int i = 0; i < 8; i++)
                    #pragma unroll
                    for (int j = 0; j < 8; j++)
                        acc[i][j] = fmaf(a[i], bb[j], acc[i][j]);
            }
            __syncthreads();
        }
    }
    // epilogue
    #pragma unroll
    for (int i = 0; i < 8; i++) {
        int gr = row0 + ty * 8 + i;
        if (gr >= NN) continue;
        #pragma unroll
        for (int j = 0; j < 8; j += 4) {
            int c = tx * 8 + j;
            float4 v;
            v.x = acc[i][j + 0] + b0[c + 0] + b1[c + 0];
            v.y = acc[i][j + 1] + b0[c + 1] + b1[c + 1];
            v.z = acc[i][j + 2] + b0[c + 2] + b1[c + 2];
            v.w = acc[i][j + 3] + b0[c + 3] + b1[c + 3];
            if (do_relu) {
                v.x = fmaxf(v.x, 0.f); v.y = fmaxf(v.y, 0.f);
                v.z = fmaxf(v.z, 0.f); v.w = fmaxf(v.w, 0.f);
            }
            *(float4*)&out[gr * 128 + c] = v;
        }
    }
}

// ---------------- pooling + linear head --------------------------------------
// One block per graph (64 blocks, 128 threads). batch is sorted.
__global__ void pool_kernel(const float* __restrict__ h, const int* __restrict__ batch,
                            const float* __restrict__ lw, const float* __restrict__ lb,
                            float* __restrict__ out)
{
    int g = blockIdx.x;
    int t = threadIdx.x;
    // lower_bound(batch, g)
    int lo = 0, hi = NN;
    while (lo < hi) { int mid = (lo + hi) >> 1; if (batch[mid] < g) lo = mid + 1; else hi = mid; }
    int beg = lo;
    lo = beg; hi = NN;
    while (lo < hi) { int mid = (lo + hi) >> 1; if (batch[mid] < g + 1) lo = mid + 1; else hi = mid; }
    int end = lo;

    __shared__ float pooled[128];
    float s = 0.f;
    for (int n = beg; n < end; n++) s += h[n * 128 + t];
    float cnt = (float)(end - beg);
    pooled[t] = s / fmaxf(cnt, 1.0f);
    __syncthreads();
    if (t < CC) {
        float o = lb[t];
        #pragma unroll 16
        for (int d = 0; d < 128; d++) o = fmaf(pooled[d], lw[d * CC + t], o);
        out[g * CC + t] = o;
    }
}

// ---------------- host launch -------------------------------------------------
extern "C" void kernel_launch(void* const* d_in, const int* in_sizes, int n_in,
                              void* d_out, int out_size)
{
    const float* x     = (const float*)d_in[0];
    const float* W     = (const float*)d_in[1];   // [L,R,D,D]
    const float* b     = (const float*)d_in[2];   // [L,R,D]
    const float* lin_w = (const float*)d_in[3];   // [D,C]
    const float* lin_b = (const float*)d_in[4];   // [C]
    const int*   ei    = (const int*)d_in[5];     // [R,2,E]
    const int*   batch = (const int*)d_in[6];     // [N]
    float* out = (float*)d_out;

    float* d_h;
    cudaGetSymbolAddress((void**)&d_h, g_h);

    // CSR build
    zero_deg_kernel<<<(RR * NN + 255) / 256, 256>>>();
    count_deg_kernel<<<(RR * EE + 255) / 256, 256>>>(ei);
    inv_sqrt_kernel<<<(RR * NN + 255) / 256, 256>>>();
    scan_kernel<<<RR, 1024>>>();
    fill_csr_kernel<<<(RR * EE + 255) / 256, 256>>>(ei);

    dim3 agg_grid((NN * 32 + 255) / 256, RR);
    int gemm_grid = (NN + 127) / 128;

    // layer 0: aggregate x -> z, gemm -> g_h (relu)
    agg_kernel<<<agg_grid, 256>>>(x);
    gemm_dual_kernel<<<gemm_grid, 256>>>(W + 0 * 128 * 128, W + 1 * 128 * 128,
                                         b + 0 * 128, b + 1 * 128, d_h, 1);
    // layer 1: aggregate g_h -> z, gemm -> g_h (no relu)
    agg_kernel<<<agg_grid, 256>>>(d_h);
    gemm_dual_kernel<<<gemm_grid, 256>>>(W + 2 * 128 * 128, W + 3 * 128 * 128,
                                         b + 2 * 128, b + 3 * 128, d_h, 0);

    // pool + head
    pool_kernel<<<GG, DD>>>(d_h, batch, lin_w, lin_b, out);
}

// round 2
// speedup vs baseline: 1.1402x; 1.1402x over previous
#include <cuda_runtime.h>
#include <cuda_fp16.h>

#define NN 50000
#define EE 800000
#define RR 2
#define DD 128
#define GG 64
#define CC 8
#define NBLK ((NN + 255) / 256)   // 196

// ---------------- scratch ----------------------------------------------------
__device__ float  g_h[NN * DD];          // final fp32 features (layer 2 out)
__device__ __half g_xh[NN * DD];         // fp16 copy of x
__device__ __half g_hh[NN * DD];         // fp16 layer-1 activations
__device__ float  g_z[RR][NN * DD];      // per-relation aggregated (fp32)
__device__ float  g_inv[RR][NN];
__device__ int    g_deg[RR][NN];
__device__ int    g_rowptr[RR][NN + 1];
__device__ int    g_fill[RR][NN];
__device__ int    g_col[RR][EE];
__device__ float  g_norm[RR][EE];
__device__ int    g_bsum[RR][NBLK];
__device__ int    g_boff[RR][NBLK];

// ---------------- CSR construction ------------------------------------------
__global__ void zero_deg_kernel() {
    int idx = blockIdx.x * blockDim.x + threadIdx.x;
    if (idx < RR * NN) ((int*)g_deg)[idx] = 0;
}

__global__ void count_deg_kernel(const int* __restrict__ ei) {
    int idx = blockIdx.x * blockDim.x + threadIdx.x;
    if (idx >= RR * EE) return;
    int r = idx / EE, e = idx % EE;
    int dst = ei[r * 2 * EE + EE + e];
    atomicAdd(&g_deg[r][dst], 1);
}

__global__ void inv_sqrt_kernel() {
    int idx = blockIdx.x * blockDim.x + threadIdx.x;
    if (idx >= RR * NN) return;
    int r = idx / NN, i = idx % NN;
    g_inv[r][i] = rsqrtf((float)g_deg[r][i] + 1.0f);
}

// Phase 1: per-block sums of 256 degrees.
__global__ void bsum_kernel() {
    int r = blockIdx.y, blk = blockIdx.x, t = threadIdx.x;
    int idx = blk * 256 + t;
    int v = (idx < NN) ? g_deg[r][idx] : 0;
    #pragma unroll
    for (int o = 16; o; o >>= 1) v += __shfl_down_sync(~0u, v, o);
    __shared__ int ws[8];
    if ((t & 31) == 0) ws[t >> 5] = v;
    __syncthreads();
    if (t == 0) {
        int s = 0;
        #pragma unroll
        for (int i = 0; i < 8; i++) s += ws[i];
        g_bsum[r][blk] = s;
    }
}

// Phase 2: one small block per relation scans the 196 block sums.
__global__ void scan_bsum_kernel() {
    int r = blockIdx.x, t = threadIdx.x;
    __shared__ int sh[256];
    int v = (t < NBLK) ? g_bsum[r][t] : 0;
    sh[t] = v;
    __syncthreads();
    #pragma unroll
    for (int o = 1; o < 256; o <<= 1) {
        int a = (t >= o) ? sh[t - o] : 0;
        __syncthreads();
        sh[t] += a;
        __syncthreads();
    }
    if (t < NBLK) g_boff[r][t] = sh[t] - v;   // exclusive
    if (t == 0) g_rowptr[r][NN] = EE;         // total = all edges
}

// Phase 3: per-block exclusive scan + global offset -> rowptr, fill cursors.
__global__ void write_rowptr_kernel() {
    int r = blockIdx.y, blk = blockIdx.x, t = threadIdx.x;
    int idx = blk * 256 + t;
    int v = (idx < NN) ? g_deg[r][idx] : 0;
    int lane = t & 31, w = t >> 5;
    int x = v;
    #pragma unroll
    for (int o = 1; o < 32; o <<= 1) {
        int y = __shfl_up_sync(~0u, x, o);
        if (lane >= o) x += y;
    }
    __shared__ int wsum[8];
    if (lane == 31) wsum[w] = x;
    __syncthreads();
    if (t == 0) {
        int run = 0;
        #pragma unroll
        for (int i = 0; i < 8; i++) { int tmp = wsum[i]; wsum[i] = run; run += tmp; }
    }
    __syncthreads();
    int exc = x - v + wsum[w] + g_boff[r][blk];
    if (idx < NN) { g_rowptr[r][idx] = exc; g_fill[r][idx] = exc; }
}

__global__ void fill_csr_kernel(const int* __restrict__ ei) {
    int idx = blockIdx.x * blockDim.x + threadIdx.x;
    if (idx >= RR * EE) return;
    int r = idx / EE, e = idx % EE;
    int src = ei[r * 2 * EE + e];
    int dst = ei[r * 2 * EE + EE + e];
    int pos = atomicAdd(&g_fill[r][dst], 1);
    g_col[r][pos]  = src;
    g_norm[r][pos] = g_inv[r][src] * g_inv[r][dst];
}

// ---------------- x -> fp16 ---------------------------------------------------
__global__ void convert_x_kernel(const float* __restrict__ x) {
    int i = blockIdx.x * blockDim.x + threadIdx.x;
    if (i >= NN * DD / 4) return;
    float4 v = ((const float4*)x)[i];
    __half2 a = __floats2half2_rn(v.x, v.y);
    __half2 b = __floats2half2_rn(v.z, v.w);
    uint2 o;
    o.x = *(unsigned*)&a;
    o.y = *(unsigned*)&b;
    ((uint2*)g_xh)[i] = o;
}

// ---------------- aggregation: z_r = A_r_norm h + d^-1 h (fp16 gather) -------
// One warp per dst node; each lane owns 4 channels (8 bytes fp16), fp32 accum.
__global__ __launch_bounds__(256) void agg_kernel(const __half* __restrict__ h) {
    int r = blockIdx.y;
    int gw = (blockIdx.x * blockDim.x + threadIdx.x) >> 5;
    int lane = threadIdx.x & 31;
    if (gw >= NN) return;
    const uint2* hv = (const uint2*)h;
    float4 acc = make_float4(0.f, 0.f, 0.f, 0.f);
    int beg = g_rowptr[r][gw], end = g_rowptr[r][gw + 1];
    for (int e = beg; e < end; e++) {
        int s    = __ldg(&g_col[r][e]);
        float nm = __ldg(&g_norm[r][e]);
        uint2 v  = __ldg(&hv[s * 32 + lane]);
        float2 fa = __half22float2(*(__half2*)&v.x);
        float2 fb = __half22float2(*(__half2*)&v.y);
        acc.x = fmaf(nm, fa.x, acc.x);
        acc.y = fmaf(nm, fa.y, acc.y);
        acc.z = fmaf(nm, fb.x, acc.z);
        acc.w = fmaf(nm, fb.y, acc.w);
    }
    float iv = g_inv[r][gw];
    float self = iv * iv;
    uint2 v = __ldg(&hv[gw * 32 + lane]);
    float2 fa = __half22float2(*(__half2*)&v.x);
    float2 fb = __half22float2(*(__half2*)&v.y);
    acc.x = fmaf(self, fa.x, acc.x);
    acc.y = fmaf(self, fa.y, acc.y);
    acc.z = fmaf(self, fb.x, acc.z);
    acc.w = fmaf(self, fb.y, acc.w);
    ((float4*)g_z[r])[gw * 32 + lane] = acc;
}

// ---------------- fused dual GEMM: out = z0 W0 + z1 W1 + (b0+b1) -------------
// Block tile 128x128, 256 threads, 8x8 register micro-tile, K-chunk = 8.
// Writes fp32 (outf) or fp16 (outh), optional relu.
__global__ __launch_bounds__(256) void gemm_dual_kernel(
    const float* __restrict__ W0, const float* __restrict__ W1,
    const float* __restrict__ b0, const float* __restrict__ b1,
    float* __restrict__ outf, __half* __restrict__ outh, int do_relu)
{
    __shared__ float As[8][128];
    __shared__ float Bs[8][128];
    int row0 = blockIdx.x * 128;
    int t = threadIdx.x;
    int tx = t & 15;
    int ty = t >> 4;
    float acc[8][8];
    #pragma unroll
    for (int i = 0; i < 8; i++)
        #pragma unroll
        for (int j = 0; j < 8; j++) acc[i][j] = 0.f;

    #pragma unroll
    for (int phase = 0; phase < 2; phase++) {
        const float* Z  = g_z[phase];
        const float* Wp = phase ? W1 : W0;
        for (int kc = 0; kc < 128; kc += 8) {
            {
                int m = t >> 1;
                int k4 = (t & 1) * 4;
                int gr = row0 + m;
                float4 v = make_float4(0.f, 0.f, 0.f, 0.f);
                if (gr < NN) v = *(const float4*)&Z[gr * 128 + kc + k4];
                As[k4 + 0][m] = v.x; As[k4 + 1][m] = v.y;
                As[k4 + 2][m] = v.z; As[k4 + 3][m] = v.w;
            }
            {
                int k  = t >> 5;
                int c4 = (t & 31) * 4;
                *(float4*)&Bs[k][c4] = *(const float4*)&Wp[(kc + k) * 128 + c4];
            }
            __syncthreads();
            #pragma unroll
            for (int kk = 0; kk < 8; kk++) {
                float4 a0  = *(float4*)&As[kk][ty * 8];
                float4 a1  = *(float4*)&As[kk][ty * 8 + 4];
                float4 bq0 = *(float4*)&Bs[kk][tx * 8];
                float4 bq1 = *(float4*)&Bs[kk][tx * 8 + 4];
                float a[8]  = {a0.x, a0.y, a0.z, a0.w, a1.x, a1.y, a1.z, a1.w};
                float bb[8] = {bq0.x, bq0.y, bq0.z, bq0.w, bq1.x, bq1.y, bq1.z, bq1.w};
                #pragma unroll
                for (int i = 0; i < 8; i++)
                    #pragma unroll
                    for (int j = 0; j < 8; j++)
                        acc[i][j] = fmaf(a[i], bb[j], acc[i][j]);
            }
            __syncthreads();
        }
    }
    #pragma unroll
    for (int i = 0; i < 8; i++) {
        int gr = row0 + ty * 8 + i;
        if (gr >= NN) continue;
        #pragma unroll
        for (int j = 0; j < 8; j += 4) {
            int c = tx * 8 + j;
            float4 v;
            v.x = acc[i][j + 0] + b0[c + 0] + b1[c + 0];
            v.y = acc[i][j + 1] + b0[c + 1] + b1[c + 1];
            v.z = acc[i][j + 2] + b0[c + 2] + b1[c + 2];
            v.w = acc[i][j + 3] + b0[c + 3] + b1[c + 3];
            if (do_relu) {
                v.x = fmaxf(v.x, 0.f); v.y = fmaxf(v.y, 0.f);
                v.z = fmaxf(v.z, 0.f); v.w = fmaxf(v.w, 0.f);
            }
            if (outh) {
                __half2 p0 = __floats2half2_rn(v.x, v.y);
                __half2 p1 = __floats2half2_rn(v.z, v.w);
                uint2 o;
                o.x = *(unsigned*)&p0;
                o.y = *(unsigned*)&p1;
                *(uint2*)&outh[gr * 128 + c] = o;
            } else {
                *(float4*)&outf[gr * 128 + c] = v;
            }
        }
    }
}

// ---------------- pooling + linear head --------------------------------------
__global__ void pool_kernel(const float* __restrict__ h, const int* __restrict__ batch,
                            const float* __restrict__ lw, const float* __restrict__ lb,
                            float* __restrict__ out)
{
    int g = blockIdx.x;
    int t = threadIdx.x;
    int lo = 0, hi = NN;
    while (lo < hi) { int mid = (lo + hi) >> 1; if (batch[mid] < g) lo = mid + 1; else hi = mid; }
    int beg = lo;
    lo = beg; hi = NN;
    while (lo < hi) { int mid = (lo + hi) >> 1; if (batch[mid] < g + 1) lo = mid + 1; else hi = mid; }
    int end = lo;

    __shared__ float pooled[128];
    float s = 0.f;
    for (int n = beg; n < end; n++) s += h[n * 128 + t];
    float cnt = (float)(end - beg);
    pooled[t] = s / fmaxf(cnt, 1.0f);
    __syncthreads();
    if (t < CC) {
        float o = lb[t];
        #pragma unroll 16
        for (int d = 0; d < 128; d++) o = fmaf(pooled[d], lw[d * CC + t], o);
        out[g * CC + t] = o;
    }
}

// ---------------- host launch -------------------------------------------------
extern "C" void kernel_launch(void* const* d_in, const int* in_sizes, int n_in,
                              void* d_out, int out_size)
{
    const float* x     = (const float*)d_in[0];
    const float* W     = (const float*)d_in[1];
    const float* b     = (const float*)d_in[2];
    const float* lin_w = (const float*)d_in[3];
    const float* lin_b = (const float*)d_in[4];
    const int*   ei    = (const int*)d_in[5];
    const int*   batch = (const int*)d_in[6];
    float* out = (float*)d_out;

    float* d_h;    cudaGetSymbolAddress((void**)&d_h, g_h);
    __half* d_xh;  cudaGetSymbolAddress((void**)&d_xh, g_xh);
    __half* d_hh;  cudaGetSymbolAddress((void**)&d_hh, g_hh);

    // CSR build
    zero_deg_kernel<<<(RR * NN + 255) / 256, 256>>>();
    count_deg_kernel<<<(RR * EE + 255) / 256, 256>>>(ei);
    inv_sqrt_kernel<<<(RR * NN + 255) / 256, 256>>>();
    bsum_kernel<<<dim3(NBLK, RR), 256>>>();
    scan_bsum_kernel<<<RR, 256>>>();
    write_rowptr_kernel<<<dim3(NBLK, RR), 256>>>();
    fill_csr_kernel<<<(RR * EE + 255) / 256, 256>>>(ei);

    // x -> fp16
    convert_x_kernel<<<(NN * DD / 4 + 255) / 256, 256>>>(x);

    dim3 agg_grid((NN * 32 + 255) / 256, RR);
    int gemm_grid = (NN + 127) / 128;

    // layer 0: aggregate fp16 x -> z (fp32), gemm -> fp16 h (relu)
    agg_kernel<<<agg_grid, 256>>>(d_xh);
    gemm_dual_kernel<<<gemm_grid, 256>>>(W + 0 * 128 * 128, W + 1 * 128 * 128,
                                         b + 0 * 128, b + 1 * 128, nullptr, d_hh, 1);
    // layer 1: aggregate fp16 h -> z, gemm -> fp32 h (no relu)
    agg_kernel<<<agg_grid, 256>>>(d_hh);
    gemm_dual_kernel<<<gemm_grid, 256>>>(W + 2 * 128 * 128, W + 3 * 128 * 128,
                                         b + 2 * 128, b + 3 * 128, d_h, nullptr, 0);

    // pool + head
    pool_kernel<<<GG, DD>>>(d_h, batch, lin_w, lin_b, out);
}

// round 4
// speedup vs baseline: 1.9567x; 1.7161x over previous
#include <cuda_runtime.h>
#include <cuda_fp16.h>

#define NN 50000
#define EE 800000
#define RR 2
#define DD 128
#define GG 64
#define CC 8
#define NBLK ((NN + 255) / 256)   // 196

// ---------------- scratch ----------------------------------------------------
__device__ float  g_h[NN * DD];          // final fp32 features (layer 2 out)
__device__ __half g_xh[NN * DD];         // fp16 copy of x
__device__ __half g_hh[NN * DD];         // fp16 layer-1 activations
__device__ __half g_zh[RR][NN * DD];     // per-relation aggregated (fp16)
__device__ __half g_WhT[RR * 2][DD * DD];// fp16 transposed weights [n][k]
__device__ float  g_inv[RR][NN];
__device__ int    g_deg[RR][NN];
__device__ int    g_rowptr[RR][NN + 1];
__device__ int    g_fill[RR][NN];
__device__ int2   g_edge[RR][EE];        // {src, __float_as_int(norm)}
__device__ int    g_bsum[RR][NBLK];
__device__ int    g_boff[RR][NBLK];

// ---------------- CSR construction ------------------------------------------
__global__ void zero_deg_kernel() {
    int idx = blockIdx.x * blockDim.x + threadIdx.x;
    if (idx < RR * NN) ((int*)g_deg)[idx] = 0;
}

__global__ void count_deg_kernel(const int* __restrict__ ei) {
    int idx = blockIdx.x * blockDim.x + threadIdx.x;
    if (idx >= RR * EE) return;
    int r = idx / EE, e = idx % EE;
    int dst = ei[r * 2 * EE + EE + e];
    atomicAdd(&g_deg[r][dst], 1);
}

__global__ void inv_sqrt_kernel() {
    int idx = blockIdx.x * blockDim.x + threadIdx.x;
    if (idx >= RR * NN) return;
    int r = idx / NN, i = idx % NN;
    g_inv[r][i] = rsqrtf((float)g_deg[r][i] + 1.0f);
}

__global__ void bsum_kernel() {
    int r = blockIdx.y, blk = blockIdx.x, t = threadIdx.x;
    int idx = blk * 256 + t;
    int v = (idx < NN) ? g_deg[r][idx] : 0;
    #pragma unroll
    for (int o = 16; o; o >>= 1) v += __shfl_down_sync(~0u, v, o);
    __shared__ int ws[8];
    if ((t & 31) == 0) ws[t >> 5] = v;
    __syncthreads();
    if (t == 0) {
        int s = 0;
        #pragma unroll
        for (int i = 0; i < 8; i++) s += ws[i];
        g_bsum[r][blk] = s;
    }
}

__global__ void scan_bsum_kernel() {
    int r = blockIdx.x, t = threadIdx.x;
    __shared__ int sh[256];
    int v = (t < NBLK) ? g_bsum[r][t] : 0;
    sh[t] = v;
    __syncthreads();
    #pragma unroll
    for (int o = 1; o < 256; o <<= 1) {
        int a = (t >= o) ? sh[t - o] : 0;
        __syncthreads();
        sh[t] += a;
        __syncthreads();
    }
    if (t < NBLK) g_boff[r][t] = sh[t] - v;
    if (t == 0) g_rowptr[r][NN] = EE;
}

__global__ void write_rowptr_kernel() {
    int r = blockIdx.y, blk = blockIdx.x, t = threadIdx.x;
    int idx = blk * 256 + t;
    int v = (idx < NN) ? g_deg[r][idx] : 0;
    int lane = t & 31, w = t >> 5;
    int x = v;
    #pragma unroll
    for (int o = 1; o < 32; o <<= 1) {
        int y = __shfl_up_sync(~0u, x, o);
        if (lane >= o) x += y;
    }
    __shared__ int wsum[8];
    if (lane == 31) wsum[w] = x;
    __syncthreads();
    if (t == 0) {
        int run = 0;
        #pragma unroll
        for (int i = 0; i < 8; i++) { int tmp = wsum[i]; wsum[i] = run; run += tmp; }
    }
    __syncthreads();
    int exc = x - v + wsum[w] + g_boff[r][blk];
    if (idx < NN) { g_rowptr[r][idx] = exc; g_fill[r][idx] = exc; }
}

__global__ void fill_csr_kernel(const int* __restrict__ ei) {
    int idx = blockIdx.x * blockDim.x + threadIdx.x;
    if (idx >= RR * EE) return;
    int r = idx / EE, e = idx % EE;
    int src = ei[r * 2 * EE + e];
    int dst = ei[r * 2 * EE + EE + e];
    int pos = atomicAdd(&g_fill[r][dst], 1);
    g_edge[r][pos] = make_int2(src, __float_as_int(g_inv[r][src] * g_inv[r][dst]));
}

// ---------------- conversions ------------------------------------------------
__global__ void convert_x_kernel(const float* __restrict__ x) {
    int i = blockIdx.x * blockDim.x + threadIdx.x;
    if (i >= NN * DD / 4) return;
    float4 v = ((const float4*)x)[i];
    __half2 a = __floats2half2_rn(v.x, v.y);
    __half2 b = __floats2half2_rn(v.z, v.w);
    uint2 o;
    o.x = *(unsigned*)&a;
    o.y = *(unsigned*)&b;
    ((uint2*)g_xh)[i] = o;
}

// W [L,R,D,D] row-major (k,n) -> g_WhT[lr][n*D + k] fp16
__global__ void convert_w_kernel(const float* __restrict__ W) {
    int i = blockIdx.x * blockDim.x + threadIdx.x;
    if (i >= 4 * DD * DD) return;
    int lr = i >> 14, rem = i & 16383, k = rem >> 7, n = rem & 127;
    g_WhT[lr][n * DD + k] = __float2half(W[i]);
}

// ---------------- aggregation: z_r = A_r_norm h + d^-1 h (fp16) --------------
// One warp per dst node; lane owns 4 channels; fp32 accumulate, fp16 store.
__global__ __launch_bounds__(256) void agg_kernel(const __half* __restrict__ h) {
    int r = blockIdx.y;
    int gw = (blockIdx.x * blockDim.x + threadIdx.x) >> 5;
    int lane = threadIdx.x & 31;
    if (gw >= NN) return;
    const uint2* hv = (const uint2*)h;
    const int2* ed = g_edge[r];
    float4 acc = make_float4(0.f, 0.f, 0.f, 0.f);
    int beg = g_rowptr[r][gw], end = g_rowptr[r][gw + 1];
    int e = beg;
    for (; e + 4 <= end; e += 4) {
        int2 p0 = __ldg(&ed[e + 0]);
        int2 p1 = __ldg(&ed[e + 1]);
        int2 p2 = __ldg(&ed[e + 2]);
        int2 p3 = __ldg(&ed[e + 3]);
        uint2 v0 = __ldg(&hv[p0.x * 32 + lane]);
        uint2 v1 = __ldg(&hv[p1.x * 32 + lane]);
        uint2 v2 = __ldg(&hv[p2.x * 32 + lane]);
        uint2 v3 = __ldg(&hv[p3.x * 32 + lane]);
        float n0 = __int_as_float(p0.y), n1 = __int_as_float(p1.y);
        float n2 = __int_as_float(p2.y), n3 = __int_as_float(p3.y);
        float2 a0 = __half22float2(*(__half2*)&v0.x), b0 = __half22float2(*(__half2*)&v0.y);
        float2 a1 = __half22float2(*(__half2*)&v1.x), b1 = __half22float2(*(__half2*)&v1.y);
        float2 a2 = __half22float2(*(__half2*)&v2.x), b2 = __half22float2(*(__half2*)&v2.y);
        float2 a3 = __half22float2(*(__half2*)&v3.x), b3 = __half22float2(*(__half2*)&v3.y);
        acc.x = fmaf(n0, a0.x, fmaf(n1, a1.x, fmaf(n2, a2.x, fmaf(n3, a3.x, acc.x))));
        acc.y = fmaf(n0, a0.y, fmaf(n1, a1.y, fmaf(n2, a2.y, fmaf(n3, a3.y, acc.y))));
        acc.z = fmaf(n0, b0.x, fmaf(n1, b1.x, fmaf(n2, b2.x, fmaf(n3, b3.x, acc.z))));
        acc.w = fmaf(n0, b0.y, fmaf(n1, b1.y, fmaf(n2, b2.y, fmaf(n3, b3.y, acc.w))));
    }
    for (; e < end; e++) {
        int2 p = __ldg(&ed[e]);
        uint2 v = __ldg(&hv[p.x * 32 + lane]);
        float nm = __int_as_float(p.y);
        float2 fa = __half22float2(*(__half2*)&v.x);
        float2 fb = __half22float2(*(__half2*)&v.y);
        acc.x = fmaf(nm, fa.x, acc.x);
        acc.y = fmaf(nm, fa.y, acc.y);
        acc.z = fmaf(nm, fb.x, acc.z);
        acc.w = fmaf(nm, fb.y, acc.w);
    }
    float iv = g_inv[r][gw];
    float self = iv * iv;
    uint2 v = __ldg(&hv[gw * 32 + lane]);
    float2 fa = __half22float2(*(__half2*)&v.x);
    float2 fb = __half22float2(*(__half2*)&v.y);
    acc.x = fmaf(self, fa.x, acc.x);
    acc.y = fmaf(self, fa.y, acc.y);
    acc.z = fmaf(self, fb.x, acc.z);
    acc.w = fmaf(self, fb.y, acc.w);
    __half2 o0 = __floats2half2_rn(acc.x, acc.y);
    __half2 o1 = __floats2half2_rn(acc.z, acc.w);
    uint2 o;
    o.x = *(unsigned*)&o0;
    o.y = *(unsigned*)&o1;
    ((uint2*)g_zh[r])[gw * 32 + lane] = o;
}

// ---------------- fused dual tensor-core GEMM --------------------------------
// out = z0 W0 + z1 W1 + (b0+b1), optional relu. Block 128x128, 8 warps,
// warp tile 32x64, mma.sync m16n8k16 f16f16f32.
__global__ __launch_bounds__(256) void gemm_dual_mma(
    const __half* __restrict__ WT0, const __half* __restrict__ WT1,
    const float* __restrict__ b0, const float* __restrict__ b1,
    const __half* __restrict__ zh0, const __half* __restrict__ zh1,
    float* __restrict__ outf, __half* __restrict__ outh, int do_relu)
{
    __shared__ __half As[128][72];   // rows x k-chunk (pad 8)
    __shared__ __half Bs[128][72];   // cols(n) x k-chunk
    int t = threadIdx.x;
    int warp = t >> 5, lane = t & 31;
    int wm = warp & 3, wn = warp >> 2;      // warp rows wm*32, cols wn*64
    int g = lane >> 2, tg = lane & 3;
    int row0 = blockIdx.x * 128;

    float acc[2][8][4];
    #pragma unroll
    for (int mt = 0; mt < 2; mt++)
        #pragma unroll
        for (int nt = 0; nt < 8; nt++)
            #pragma unroll
            for (int q = 0; q < 4; q++) acc[mt][nt][q] = 0.f;

    #pragma unroll
    for (int phase = 0; phase < 2; phase++) {
        const __half* Z  = phase ? zh1 : zh0;
        const __half* WT = phase ? WT1 : WT0;
        #pragma unroll
        for (int kc = 0; kc < 128; kc += 64) {
            __syncthreads();
            for (int i = t; i < 128 * 8; i += 256) {
                int row = i >> 3, c8 = (i & 7) * 8;
                uint4 v = make_uint4(0, 0, 0, 0);
                int gr = row0 + row;
                if (gr < NN) v = *(const uint4*)&Z[gr * 128 + kc + c8];
                *(uint4*)&As[row][c8] = v;
            }
            for (int i = t; i < 128 * 8; i += 256) {
                int n = i >> 3, c8 = (i & 7) * 8;
                *(uint4*)&Bs[n][c8] = *(const uint4*)&WT[n * 128 + kc + c8];
            }
            __syncthreads();
            #pragma unroll
            for (int kk = 0; kk < 4; kk++) {
                int k0 = kk * 16;
                unsigned a[2][4];
                #pragma unroll
                for (int mt = 0; mt < 2; mt++) {
                    int rb = wm * 32 + mt * 16;
                    a[mt][0] = *(unsigned*)&As[rb + g][k0 + tg * 2];
                    a[mt][1] = *(unsigned*)&As[rb + g + 8][k0 + tg * 2];
                    a[mt][2] = *(unsigned*)&As[rb + g][k0 + tg * 2 + 8];
                    a[mt][3] = *(unsigned*)&As[rb + g + 8][k0 + tg * 2 + 8];
                }
                #pragma unroll
                for (int nt = 0; nt < 8; nt++) {
                    int cb = wn * 64 + nt * 8 + g;
                    unsigned bf0 = *(unsigned*)&Bs[cb][k0 + tg * 2];
                    unsigned bf1 = *(unsigned*)&Bs[cb][k0 + tg * 2 + 8];
                    #pragma unroll
                    for (int mt = 0; mt < 2; mt++) {
                        asm volatile(
                            "mma.sync.aligned.m16n8k16.row.col.f32.f16.f16.f32 "
                            "{%0,%1,%2,%3}, {%4,%5,%6,%7}, {%8,%9}, {%0,%1,%2,%3};\n"
                            : "+f"(acc[mt][nt][0]), "+f"(acc[mt][nt][1]),
                              "+f"(acc[mt][nt][2]), "+f"(acc[mt][nt][3])
                            : "r"(a[mt][0]), "r"(a[mt][1]), "r"(a[mt][2]), "r"(a[mt][3]),
                              "r"(bf0), "r"(bf1));
                    }
                }
            }
        }
    }
    // epilogue
    #pragma unroll
    for (int mt = 0; mt < 2; mt++) {
        int r_lo = row0 + wm * 32 + mt * 16 + g;
        int r_hi = r_lo + 8;
        #pragma unroll
        for (int nt = 0; nt < 8; nt++) {
            int c = wn * 64 + nt * 8 + tg * 2;
            float bia0 = b0[c] + b1[c];
            float bia1 = b0[c + 1] + b1[c + 1];
            float v0 = acc[mt][nt][0] + bia0;
            float v1 = acc[mt][nt][1] + bia1;
            float v2 = acc[mt][nt][2] + bia0;
            float v3 = acc[mt][nt][3] + bia1;
            if (do_relu) {
                v0 = fmaxf(v0, 0.f); v1 = fmaxf(v1, 0.f);
                v2 = fmaxf(v2, 0.f); v3 = fmaxf(v3, 0.f);
            }
            if (outh) {
                if (r_lo < NN) {
                    __half2 p = __floats2half2_rn(v0, v1);
                    *(__half2*)&outh[r_lo * 128 + c] = p;
                }
                if (r_hi < NN) {
                    __half2 p = __floats2half2_rn(v2, v3);
                    *(__half2*)&outh[r_hi * 128 + c] = p;
                }
            } else {
                if (r_lo < NN) *(float2*)&outf[r_lo * 128 + c] = make_float2(v0, v1);
                if (r_hi < NN) *(float2*)&outf[r_hi * 128 + c] = make_float2(v2, v3);
            }
        }
    }
}

// ---------------- pooling + linear head --------------------------------------
__global__ void pool_kernel(const float* __restrict__ h, const int* __restrict__ batch,
                            const float* __restrict__ lw, const float* __restrict__ lb,
                            float* __restrict__ out)
{
    int g = blockIdx.x;
    int t = threadIdx.x;
    int lo = 0, hi = NN;
    while (lo < hi) { int mid = (lo + hi) >> 1; if (batch[mid] < g) lo = mid + 1; else hi = mid; }
    int beg = lo;
    lo = beg; hi = NN;
    while (lo < hi) { int mid = (lo + hi) >> 1; if (batch[mid] < g + 1) lo = mid + 1; else hi = mid; }
    int end = lo;

    __shared__ float pooled[128];
    float s = 0.f;
    for (int n = beg; n < end; n++) s += h[n * 128 + t];
    float cnt = (float)(end - beg);
    pooled[t] = s / fmaxf(cnt, 1.0f);
    __syncthreads();
    if (t < CC) {
        float o = lb[t];
        #pragma unroll 16
        for (int d = 0; d < 128; d++) o = fmaf(pooled[d], lw[d * CC + t], o);
        out[g * CC + t] = o;
    }
}

// ---------------- host launch -------------------------------------------------
extern "C" void kernel_launch(void* const* d_in, const int* in_sizes, int n_in,
                              void* d_out, int out_size)
{
    const float* x     = (const float*)d_in[0];
    const float* W     = (const float*)d_in[1];
    const float* b     = (const float*)d_in[2];
    const float* lin_w = (const float*)d_in[3];
    const float* lin_b = (const float*)d_in[4];
    const int*   ei    = (const int*)d_in[5];
    const int*   batch = (const int*)d_in[6];
    float* out = (float*)d_out;

    float*  d_h;   cudaGetSymbolAddress((void**)&d_h, g_h);
    __half* d_xh;  cudaGetSymbolAddress((void**)&d_xh, g_xh);
    __half* d_hh;  cudaGetSymbolAddress((void**)&d_hh, g_hh);
    __half* d_zh;  cudaGetSymbolAddress((void**)&d_zh, g_zh);
    __half* d_wt;  cudaGetSymbolAddress((void**)&d_wt, g_WhT);

    // CSR build
    zero_deg_kernel<<<(RR * NN + 255) / 256, 256>>>();
    count_deg_kernel<<<(RR * EE + 255) / 256, 256>>>(ei);
    inv_sqrt_kernel<<<(RR * NN + 255) / 256, 256>>>();
    bsum_kernel<<<dim3(NBLK, RR), 256>>>();
    scan_bsum_kernel<<<RR, 256>>>();
    write_rowptr_kernel<<<dim3(NBLK, RR), 256>>>();
    fill_csr_kernel<<<(RR * EE + 255) / 256, 256>>>(ei);

    // conversions
    convert_x_kernel<<<(NN * DD / 4 + 255) / 256, 256>>>(x);
    convert_w_kernel<<<(4 * DD * DD + 255) / 256, 256>>>(W);

    dim3 agg_grid((NN * 32 + 255) / 256, RR);
    int gemm_grid = (NN + 127) / 128;
    const __half* z0 = d_zh;
    const __half* z1 = d_zh + NN * DD;

    // layer 0
    agg_kernel<<<agg_grid, 256>>>(d_xh);
    gemm_dual_mma<<<gemm_grid, 256>>>(d_wt + 0 * DD * DD, d_wt + 1 * DD * DD,
                                      b + 0 * DD, b + 1 * DD, z0, z1,
                                      nullptr, d_hh, 1);
    // layer 1
    agg_kernel<<<agg_grid, 256>>>(d_hh);
    gemm_dual_mma<<<gemm_grid, 256>>>(d_wt + 2 * DD * DD, d_wt + 3 * DD * DD,
                                      b + 2 * DD, b + 3 * DD, z0, z1,
                                      d_h, nullptr, 0);

    // pool + head
    pool_kernel<<<GG, DD>>>(d_h, batch, lin_w, lin_b, out);
}

// round 5
// speedup vs baseline: 2.1133x; 1.0800x over previous
#include <cuda_runtime.h>
#include <cuda_fp16.h>

#define NN 50000
#define EE 800000
#define RR 2
#define DD 128
#define GG 64
#define CC 8
#define NBLK ((NN + 255) / 256)   // 196

// ---------------- scratch ----------------------------------------------------
__device__ __half g_xh[NN * DD];         // fp16 x; later reused for final h
__device__ __half g_hh[NN * DD];         // fp16 layer-1 activations
__device__ __half g_zh[RR][NN * DD];     // per-relation aggregated (fp16)
__device__ __half g_WhT[RR * 2][DD * DD];// fp16 transposed weights [n][k]
__device__ float  g_inv[RR][NN];
__device__ int    g_deg[RR][NN];
__device__ int    g_rowptr[RR][NN + 1];
__device__ int    g_fill[RR][NN];
__device__ int2   g_edge[RR][EE];        // {src, __float_as_int(norm)}
__device__ int    g_bsum[RR][NBLK];
__device__ float  g_gsum[GG * DD];       // pooled partial sums

// ---------------- prep: zero deg/gsum, convert x + W -------------------------
__global__ void prep_kernel(const float* __restrict__ x, const float* __restrict__ W) {
    int i = blockIdx.x * blockDim.x + threadIdx.x;
    if (i < NN * DD / 4) {
        float4 v = ((const float4*)x)[i];
        __half2 a = __floats2half2_rn(v.x, v.y);
        __half2 b = __floats2half2_rn(v.z, v.w);
        uint2 o;
        o.x = *(unsigned*)&a;
        o.y = *(unsigned*)&b;
        ((uint2*)g_xh)[i] = o;
    }
    if (i < 4 * DD * DD) {   // W [L,R,D,D] (k,n) -> WhT[lr][n*D+k]
        int lr = i >> 14, rem = i & 16383, k = rem >> 7, n = rem & 127;
        g_WhT[lr][n * DD + k] = __float2half(W[i]);
    }
    if (i < RR * NN) ((int*)g_deg)[i] = 0;
    if (i < GG * DD) g_gsum[i] = 0.f;
}

// ---------------- CSR construction ------------------------------------------
__global__ void count_deg_kernel(const int* __restrict__ ei) {
    int idx = blockIdx.x * blockDim.x + threadIdx.x;
    if (idx >= RR * EE) return;
    int r = idx / EE, e = idx % EE;
    int dst = ei[r * 2 * EE + EE + e];
    atomicAdd(&g_deg[r][dst], 1);
}

// block sums of degrees + inv sqrt (fused)
__global__ void bsum_kernel() {
    int r = blockIdx.y, blk = blockIdx.x, t = threadIdx.x;
    int idx = blk * 256 + t;
    int v = (idx < NN) ? g_deg[r][idx] : 0;
    if (idx < NN) g_inv[r][idx] = rsqrtf((float)v + 1.0f);
    int s = v;
    #pragma unroll
    for (int o = 16; o; o >>= 1) s += __shfl_down_sync(~0u, s, o);
    __shared__ int ws[8];
    if ((t & 31) == 0) ws[t >> 5] = s;
    __syncthreads();
    if (t == 0) {
        int tot = 0;
        #pragma unroll
        for (int i = 0; i < 8; i++) tot += ws[i];
        g_bsum[r][blk] = tot;
    }
}

// every block redundantly scans the 196 block sums, then scans its own 256 degs
__global__ void write_rowptr_kernel() {
    int r = blockIdx.y, blk = blockIdx.x, t = threadIdx.x;
    __shared__ int sb[256], sorig[256];
    int bv = (t < NBLK) ? g_bsum[r][t] : 0;
    sb[t] = bv; sorig[t] = bv;
    __syncthreads();
    #pragma unroll
    for (int o = 1; o < 256; o <<= 1) {
        int a = (t >= o) ? sb[t - o] : 0;
        __syncthreads();
        sb[t] += a;
        __syncthreads();
    }
    int boff = sb[blk] - sorig[blk];   // exclusive prefix for this block

    int idx = blk * 256 + t;
    int v = (idx < NN) ? g_deg[r][idx] : 0;
    int lane = t & 31, w = t >> 5;
    int x = v;
    #pragma unroll
    for (int o = 1; o < 32; o <<= 1) {
        int y = __shfl_up_sync(~0u, x, o);
        if (lane >= o) x += y;
    }
    __shared__ int wsum[8];
    if (lane == 31) wsum[w] = x;
    __syncthreads();
    if (t == 0) {
        int run = 0;
        #pragma unroll
        for (int i = 0; i < 8; i++) { int tmp = wsum[i]; wsum[i] = run; run += tmp; }
    }
    __syncthreads();
    int exc = x - v + wsum[w] + boff;
    if (idx < NN) { g_rowptr[r][idx] = exc; g_fill[r][idx] = exc; }
    if (blk == 0 && t == 0) g_rowptr[r][NN] = EE;
}

__global__ void fill_csr_kernel(const int* __restrict__ ei) {
    int idx = blockIdx.x * blockDim.x + threadIdx.x;
    if (idx >= RR * EE) return;
    int r = idx / EE, e = idx % EE;
    int src = ei[r * 2 * EE + e];
    int dst = ei[r * 2 * EE + EE + e];
    int pos = atomicAdd(&g_fill[r][dst], 1);
    g_edge[r][pos] = make_int2(src, __float_as_int(g_inv[r][src] * g_inv[r][dst]));
}

// ---------------- aggregation: z_r = A_r_norm h + d^-1 h (fp16) --------------
// One warp per dst node; lane owns 4 channels; fp32 accumulate, fp16 store.
__global__ __launch_bounds__(256) void agg_kernel(const __half* __restrict__ h) {
    int r = blockIdx.y;
    int gw = (blockIdx.x * blockDim.x + threadIdx.x) >> 5;
    int lane = threadIdx.x & 31;
    if (gw >= NN) return;
    const uint2* hv = (const uint2*)h;
    const int2* ed = g_edge[r];
    float4 acc = make_float4(0.f, 0.f, 0.f, 0.f);
    int beg = g_rowptr[r][gw], end = g_rowptr[r][gw + 1];
    int e = beg;
    for (; e + 8 <= end; e += 8) {
        int2 p[8]; uint2 v[8];
        #pragma unroll
        for (int u = 0; u < 8; u++) p[u] = __ldg(&ed[e + u]);
        #pragma unroll
        for (int u = 0; u < 8; u++) v[u] = __ldg(&hv[p[u].x * 32 + lane]);
        #pragma unroll
        for (int u = 0; u < 8; u++) {
            float nm = __int_as_float(p[u].y);
            float2 fa = __half22float2(*(__half2*)&v[u].x);
            float2 fb = __half22float2(*(__half2*)&v[u].y);
            acc.x = fmaf(nm, fa.x, acc.x);
            acc.y = fmaf(nm, fa.y, acc.y);
            acc.z = fmaf(nm, fb.x, acc.z);
            acc.w = fmaf(nm, fb.y, acc.w);
        }
    }
    for (; e < end; e++) {
        int2 p = __ldg(&ed[e]);
        uint2 v = __ldg(&hv[p.x * 32 + lane]);
        float nm = __int_as_float(p.y);
        float2 fa = __half22float2(*(__half2*)&v.x);
        float2 fb = __half22float2(*(__half2*)&v.y);
        acc.x = fmaf(nm, fa.x, acc.x);
        acc.y = fmaf(nm, fa.y, acc.y);
        acc.z = fmaf(nm, fb.x, acc.z);
        acc.w = fmaf(nm, fb.y, acc.w);
    }
    float iv = g_inv[r][gw];
    float self = iv * iv;
    uint2 v = __ldg(&hv[gw * 32 + lane]);
    float2 fa = __half22float2(*(__half2*)&v.x);
    float2 fb = __half22float2(*(__half2*)&v.y);
    acc.x = fmaf(self, fa.x, acc.x);
    acc.y = fmaf(self, fa.y, acc.y);
    acc.z = fmaf(self, fb.x, acc.z);
    acc.w = fmaf(self, fb.y, acc.w);
    __half2 o0 = __floats2half2_rn(acc.x, acc.y);
    __half2 o1 = __floats2half2_rn(acc.z, acc.w);
    uint2 o;
    o.x = *(unsigned*)&o0;
    o.y = *(unsigned*)&o1;
    ((uint2*)g_zh[r])[gw * 32 + lane] = o;
}

// ---------------- fused dual tensor-core GEMM --------------------------------
// out = z0 W0 + z1 W1 + (b0+b1), optional relu, fp16 out. Block 128x128,
// 8 warps, warp tile 32x64, mma.sync m16n8k16 f16f16f32.
__global__ __launch_bounds__(256) void gemm_dual_mma(
    const __half* __restrict__ WT0, const __half* __restrict__ WT1,
    const float* __restrict__ b0, const float* __restrict__ b1,
    const __half* __restrict__ zh0, const __half* __restrict__ zh1,
    __half* __restrict__ outh, int do_relu)
{
    __shared__ __half As[128][72];
    __shared__ __half Bs[128][72];
    int t = threadIdx.x;
    int warp = t >> 5, lane = t & 31;
    int wm = warp & 3, wn = warp >> 2;
    int g = lane >> 2, tg = lane & 3;
    int row0 = blockIdx.x * 128;

    float acc[2][8][4];
    #pragma unroll
    for (int mt = 0; mt < 2; mt++)
        #pragma unroll
        for (int nt = 0; nt < 8; nt++)
            #pragma unroll
            for (int q = 0; q < 4; q++) acc[mt][nt][q] = 0.f;

    #pragma unroll
    for (int phase = 0; phase < 2; phase++) {
        const __half* Z  = phase ? zh1 : zh0;
        const __half* WT = phase ? WT1 : WT0;
        #pragma unroll
        for (int kc = 0; kc < 128; kc += 64) {
            __syncthreads();
            for (int i = t; i < 128 * 8; i += 256) {
                int row = i >> 3, c8 = (i & 7) * 8;
                uint4 v = make_uint4(0, 0, 0, 0);
                int gr = row0 + row;
                if (gr < NN) v = *(const uint4*)&Z[gr * 128 + kc + c8];
                *(uint4*)&As[row][c8] = v;
            }
            for (int i = t; i < 128 * 8; i += 256) {
                int n = i >> 3, c8 = (i & 7) * 8;
                *(uint4*)&Bs[n][c8] = *(const uint4*)&WT[n * 128 + kc + c8];
            }
            __syncthreads();
            #pragma unroll
            for (int kk = 0; kk < 4; kk++) {
                int k0 = kk * 16;
                unsigned a[2][4];
                #pragma unroll
                for (int mt = 0; mt < 2; mt++) {
                    int rb = wm * 32 + mt * 16;
                    a[mt][0] = *(unsigned*)&As[rb + g][k0 + tg * 2];
                    a[mt][1] = *(unsigned*)&As[rb + g + 8][k0 + tg * 2];
                    a[mt][2] = *(unsigned*)&As[rb + g][k0 + tg * 2 + 8];
                    a[mt][3] = *(unsigned*)&As[rb + g + 8][k0 + tg * 2 + 8];
                }
                #pragma unroll
                for (int nt = 0; nt < 8; nt++) {
                    int cb = wn * 64 + nt * 8 + g;
                    unsigned bf0 = *(unsigned*)&Bs[cb][k0 + tg * 2];
                    unsigned bf1 = *(unsigned*)&Bs[cb][k0 + tg * 2 + 8];
                    #pragma unroll
                    for (int mt = 0; mt < 2; mt++) {
                        asm volatile(
                            "mma.sync.aligned.m16n8k16.row.col.f32.f16.f16.f32 "
                            "{%0,%1,%2,%3}, {%4,%5,%6,%7}, {%8,%9}, {%0,%1,%2,%3};\n"
                            : "+f"(acc[mt][nt][0]), "+f"(acc[mt][nt][1]),
                              "+f"(acc[mt][nt][2]), "+f"(acc[mt][nt][3])
                            : "r"(a[mt][0]), "r"(a[mt][1]), "r"(a[mt][2]), "r"(a[mt][3]),
                              "r"(bf0), "r"(bf1));
                    }
                }
            }
        }
    }
    #pragma unroll
    for (int mt = 0; mt < 2; mt++) {
        int r_lo = row0 + wm * 32 + mt * 16 + g;
        int r_hi = r_lo + 8;
        #pragma unroll
        for (int nt = 0; nt < 8; nt++) {
            int c = wn * 64 + nt * 8 + tg * 2;
            float bia0 = b0[c] + b1[c];
            float bia1 = b0[c + 1] + b1[c + 1];
            float v0 = acc[mt][nt][0] + bia0;
            float v1 = acc[mt][nt][1] + bia1;
            float v2 = acc[mt][nt][2] + bia0;
            float v3 = acc[mt][nt][3] + bia1;
            if (do_relu) {
                v0 = fmaxf(v0, 0.f); v1 = fmaxf(v1, 0.f);
                v2 = fmaxf(v2, 0.f); v3 = fmaxf(v3, 0.f);
            }
            if (r_lo < NN) {
                __half2 p = __floats2half2_rn(v0, v1);
                *(__half2*)&outh[r_lo * 128 + c] = p;
            }
            if (r_hi < NN) {
                __half2 p = __floats2half2_rn(v2, v3);
                *(__half2*)&outh[r_hi * 128 + c] = p;
            }
        }
    }
}

// ---------------- pooling stage 1: full-chip partial sums --------------------
// 128 rows per block, 128 threads (t = channel); batch sorted -> few segments.
__global__ __launch_bounds__(128) void pool1_kernel(const __half* __restrict__ h,
                                                    const int* __restrict__ batch) {
    int t = threadIdx.x;
    int row0 = blockIdx.x * 128;
    int row_end = row0 + 128 > NN ? NN : row0 + 128;
    if (row0 >= NN) return;
    float run = 0.f;
    int cur = batch[row0];
    for (int n = row0; n < row_end; n++) {
        int gid = __ldg(&batch[n]);
        if (gid != cur) {
            atomicAdd(&g_gsum[cur * DD + t], run);
            run = 0.f;
            cur = gid;
        }
        run += __half2float(h[n * DD + t]);
    }
    atomicAdd(&g_gsum[cur * DD + t], run);
}

// ---------------- pooling stage 2: finalize + linear head --------------------
__global__ void pool2_kernel(const int* __restrict__ batch,
                             const float* __restrict__ lw, const float* __restrict__ lb,
                             float* __restrict__ out) {
    int g = blockIdx.x;
    int t = threadIdx.x;
    int lo = 0, hi = NN;
    while (lo < hi) { int m = (lo + hi) >> 1; if (batch[m] < g) lo = m + 1; else hi = m; }
    int beg = lo;
    lo = beg; hi = NN;
    while (lo < hi) { int m = (lo + hi) >> 1; if (batch[m] < g + 1) lo = m + 1; else hi = m; }
    int cnt = lo - beg;

    __shared__ float pooled[DD];
    pooled[t] = g_gsum[g * DD + t] / fmaxf((float)cnt, 1.0f);
    __syncthreads();
    if (t < CC) {
        float o = lb[t];
        #pragma unroll 16
        for (int d = 0; d < DD; d++) o = fmaf(pooled[d], lw[d * CC + t], o);
        out[g * CC + t] = o;
    }
}

// ---------------- host launch -------------------------------------------------
extern "C" void kernel_launch(void* const* d_in, const int* in_sizes, int n_in,
                              void* d_out, int out_size)
{
    const float* x     = (const float*)d_in[0];
    const float* W     = (const float*)d_in[1];
    const float* b     = (const float*)d_in[2];
    const float* lin_w = (const float*)d_in[3];
    const float* lin_b = (const float*)d_in[4];
    const int*   ei    = (const int*)d_in[5];
    const int*   batch = (const int*)d_in[6];
    float* out = (float*)d_out;

    __half* d_xh;  cudaGetSymbolAddress((void**)&d_xh, g_xh);
    __half* d_hh;  cudaGetSymbolAddress((void**)&d_hh, g_hh);
    __half* d_zh;  cudaGetSymbolAddress((void**)&d_zh, g_zh);
    __half* d_wt;  cudaGetSymbolAddress((void**)&d_wt, g_WhT);

    // 1. prep: zero deg/gsum, convert x + W
    prep_kernel<<<(NN * DD / 4 + 255) / 256, 256>>>(x, W);
    // 2-5. CSR build
    count_deg_kernel<<<(RR * EE + 255) / 256, 256>>>(ei);
    bsum_kernel<<<dim3(NBLK, RR), 256>>>();
    write_rowptr_kernel<<<dim3(NBLK, RR), 256>>>();
    fill_csr_kernel<<<(RR * EE + 255) / 256, 256>>>(ei);

    dim3 agg_grid((NN * 32 + 255) / 256, RR);
    int gemm_grid = (NN + 127) / 128;
    const __half* z0 = d_zh;
    const __half* z1 = d_zh + NN * DD;

    // 6-7. layer 0
    agg_kernel<<<agg_grid, 256>>>(d_xh);
    gemm_dual_mma<<<gemm_grid, 256>>>(d_wt + 0 * DD * DD, d_wt + 1 * DD * DD,
                                      b + 0 * DD, b + 1 * DD, z0, z1, d_hh, 1);
    // 8-9. layer 1 (final h -> g_xh, reused)
    agg_kernel<<<agg_grid, 256>>>(d_hh);
    gemm_dual_mma<<<gemm_grid, 256>>>(d_wt + 2 * DD * DD, d_wt + 3 * DD * DD,
                                      b + 2 * DD, b + 3 * DD, z0, z1, d_xh, 0);

    // 10-11. pool + head
    pool1_kernel<<<(NN + 127) / 128, 128>>>(d_xh, batch);
    pool2_kernel<<<GG, DD>>>(batch, lin_w, lin_b, out);
}

// round 6
// speedup vs baseline: 2.1136x; 1.0001x over previous
#include <cuda_runtime.h>
#include <cuda_fp16.h>

#define NN 50000
#define EE 800000
#define RR 2
#define DD 128
#define GG 64
#define CC 8
#define NBLK ((NN + 255) / 256)   // 196
#define E4 (EE / 4)               // 200000

// ---------------- scratch ----------------------------------------------------
__device__ __half g_xh[NN * DD];         // fp16 x; later reused for final h
__device__ __half g_hh[NN * DD];         // fp16 layer-1 activations
__device__ __half g_zh[RR][NN * DD];     // per-relation aggregated (fp16)
__device__ __half g_WhT[RR * 2][DD * DD];// fp16 transposed weights [n][k]
__device__ float  g_inv[RR][NN];
__device__ int    g_deg[RR][NN];
__device__ int    g_rowptr[RR][NN + 1];
__device__ int    g_fill[RR][NN];
__device__ int2   g_edge[RR][EE];        // {src, __float_as_int(norm)}
__device__ int    g_bsum[RR][NBLK];
__device__ float  g_gsum[GG * DD];       // pooled partial sums

// ---------------- prep: zero deg/gsum, convert x + W -------------------------
__global__ void prep_kernel(const float* __restrict__ x, const float* __restrict__ W) {
    int i = blockIdx.x * blockDim.x + threadIdx.x;
    if (i < NN * DD / 4) {
        float4 v = ((const float4*)x)[i];
        __half2 a = __floats2half2_rn(v.x, v.y);
        __half2 b = __floats2half2_rn(v.z, v.w);
        uint2 o;
        o.x = *(unsigned*)&a;
        o.y = *(unsigned*)&b;
        ((uint2*)g_xh)[i] = o;
    }
    if (i < 4 * DD * DD) {   // W [L,R,D,D] (k,n) -> WhT[lr][n*D+k]
        int lr = i >> 14, rem = i & 16383, k = rem >> 7, n = rem & 127;
        g_WhT[lr][n * DD + k] = __float2half(W[i]);
    }
    if (i < RR * NN) ((int*)g_deg)[i] = 0;
    if (i < GG * DD) g_gsum[i] = 0.f;
}

// ---------------- CSR construction ------------------------------------------
// 4 edges per thread (int4 reads of the dst row)
__global__ void count_deg_kernel(const int* __restrict__ ei) {
    int idx = blockIdx.x * blockDim.x + threadIdx.x;
    if (idx >= RR * E4) return;
    int r = idx / E4, e4 = idx % E4;
    int4 d = __ldg(&((const int4*)(ei + r * 2 * EE + EE))[e4]);
    atomicAdd(&g_deg[r][d.x], 1);
    atomicAdd(&g_deg[r][d.y], 1);
    atomicAdd(&g_deg[r][d.z], 1);
    atomicAdd(&g_deg[r][d.w], 1);
}

// block sums of degrees + inv sqrt (fused)
__global__ void bsum_kernel() {
    int r = blockIdx.y, blk = blockIdx.x, t = threadIdx.x;
    int idx = blk * 256 + t;
    int v = (idx < NN) ? g_deg[r][idx] : 0;
    if (idx < NN) g_inv[r][idx] = rsqrtf((float)v + 1.0f);
    int s = v;
    #pragma unroll
    for (int o = 16; o; o >>= 1) s += __shfl_down_sync(~0u, s, o);
    __shared__ int ws[8];
    if ((t & 31) == 0) ws[t >> 5] = s;
    __syncthreads();
    if (t == 0) {
        int tot = 0;
        #pragma unroll
        for (int i = 0; i < 8; i++) tot += ws[i];
        g_bsum[r][blk] = tot;
    }
}

// every block redundantly scans the 196 block sums, then its own 256 degrees
__global__ void write_rowptr_kernel() {
    int r = blockIdx.y, blk = blockIdx.x, t = threadIdx.x;
    __shared__ int sb[256], sorig[256];
    int bv = (t < NBLK) ? g_bsum[r][t] : 0;
    sb[t] = bv; sorig[t] = bv;
    __syncthreads();
    #pragma unroll
    for (int o = 1; o < 256; o <<= 1) {
        int a = (t >= o) ? sb[t - o] : 0;
        __syncthreads();
        sb[t] += a;
        __syncthreads();
    }
    int boff = sb[blk] - sorig[blk];

    int idx = blk * 256 + t;
    int v = (idx < NN) ? g_deg[r][idx] : 0;
    int lane = t & 31, w = t >> 5;
    int x = v;
    #pragma unroll
    for (int o = 1; o < 32; o <<= 1) {
        int y = __shfl_up_sync(~0u, x, o);
        if (lane >= o) x += y;
    }
    __shared__ int wsum[8];
    if (lane == 31) wsum[w] = x;
    __syncthreads();
    if (t == 0) {
        int run = 0;
        #pragma unroll
        for (int i = 0; i < 8; i++) { int tmp = wsum[i]; wsum[i] = run; run += tmp; }
    }
    __syncthreads();
    int exc = x - v + wsum[w] + boff;
    if (idx < NN) { g_rowptr[r][idx] = exc; g_fill[r][idx] = exc; }
    if (blk == 0 && t == 0) g_rowptr[r][NN] = EE;
}

// 4 edges per thread (int4 reads of src and dst rows)
__global__ void fill_csr_kernel(const int* __restrict__ ei) {
    int idx = blockIdx.x * blockDim.x + threadIdx.x;
    if (idx >= RR * E4) return;
    int r = idx / E4, e4 = idx % E4;
    int4 s = __ldg(&((const int4*)(ei + r * 2 * EE))[e4]);
    int4 d = __ldg(&((const int4*)(ei + r * 2 * EE + EE))[e4]);
    const float* inv = g_inv[r];
    int2* ed = g_edge[r];
    int p;
    p = atomicAdd(&g_fill[r][d.x], 1);
    ed[p] = make_int2(s.x, __float_as_int(inv[s.x] * inv[d.x]));
    p = atomicAdd(&g_fill[r][d.y], 1);
    ed[p] = make_int2(s.y, __float_as_int(inv[s.y] * inv[d.y]));
    p = atomicAdd(&g_fill[r][d.z], 1);
    ed[p] = make_int2(s.z, __float_as_int(inv[s.z] * inv[d.z]));
    p = atomicAdd(&g_fill[r][d.w], 1);
    ed[p] = make_int2(s.w, __float_as_int(inv[s.w] * inv[d.w]));
}

// ---------------- aggregation: z_r = A_r_norm h + d^-1 h (fp16) --------------
__global__ __launch_bounds__(256) void agg_kernel(const __half* __restrict__ h) {
    int r = blockIdx.y;
    int gw = (blockIdx.x * blockDim.x + threadIdx.x) >> 5;
    int lane = threadIdx.x & 31;
    if (gw >= NN) return;
    const uint2* hv = (const uint2*)h;
    const int2* ed = g_edge[r];
    float4 acc = make_float4(0.f, 0.f, 0.f, 0.f);
    int beg = g_rowptr[r][gw], end = g_rowptr[r][gw + 1];
    int e = beg;
    for (; e + 8 <= end; e += 8) {
        int2 p[8]; uint2 v[8];
        #pragma unroll
        for (int u = 0; u < 8; u++) p[u] = __ldg(&ed[e + u]);
        #pragma unroll
        for (int u = 0; u < 8; u++) v[u] = __ldg(&hv[p[u].x * 32 + lane]);
        #pragma unroll
        for (int u = 0; u < 8; u++) {
            float nm = __int_as_float(p[u].y);
            float2 fa = __half22float2(*(__half2*)&v[u].x);
            float2 fb = __half22float2(*(__half2*)&v[u].y);
            acc.x = fmaf(nm, fa.x, acc.x);
            acc.y = fmaf(nm, fa.y, acc.y);
            acc.z = fmaf(nm, fb.x, acc.z);
            acc.w = fmaf(nm, fb.y, acc.w);
        }
    }
    for (; e + 2 <= end; e += 2) {
        int2 p0 = __ldg(&ed[e]);
        int2 p1 = __ldg(&ed[e + 1]);
        uint2 v0 = __ldg(&hv[p0.x * 32 + lane]);
        uint2 v1 = __ldg(&hv[p1.x * 32 + lane]);
        float n0 = __int_as_float(p0.y), n1 = __int_as_float(p1.y);
        float2 a0 = __half22float2(*(__half2*)&v0.x), b0 = __half22float2(*(__half2*)&v0.y);
        float2 a1 = __half22float2(*(__half2*)&v1.x), b1 = __half22float2(*(__half2*)&v1.y);
        acc.x = fmaf(n0, a0.x, fmaf(n1, a1.x, acc.x));
        acc.y = fmaf(n0, a0.y, fmaf(n1, a1.y, acc.y));
        acc.z = fmaf(n0, b0.x, fmaf(n1, b1.x, acc.z));
        acc.w = fmaf(n0, b0.y, fmaf(n1, b1.y, acc.w));
    }
    if (e < end) {
        int2 p = __ldg(&ed[e]);
        uint2 v = __ldg(&hv[p.x * 32 + lane]);
        float nm = __int_as_float(p.y);
        float2 fa = __half22float2(*(__half2*)&v.x);
        float2 fb = __half22float2(*(__half2*)&v.y);
        acc.x = fmaf(nm, fa.x, acc.x);
        acc.y = fmaf(nm, fa.y, acc.y);
        acc.z = fmaf(nm, fb.x, acc.z);
        acc.w = fmaf(nm, fb.y, acc.w);
    }
    float iv = g_inv[r][gw];
    float self = iv * iv;
    uint2 v = __ldg(&hv[gw * 32 + lane]);
    float2 fa = __half22float2(*(__half2*)&v.x);
    float2 fb = __half22float2(*(__half2*)&v.y);
    acc.x = fmaf(self, fa.x, acc.x);
    acc.y = fmaf(self, fa.y, acc.y);
    acc.z = fmaf(self, fb.x, acc.z);
    acc.w = fmaf(self, fb.y, acc.w);
    __half2 o0 = __floats2half2_rn(acc.x, acc.y);
    __half2 o1 = __floats2half2_rn(acc.z, acc.w);
    uint2 o;
    o.x = *(unsigned*)&o0;
    o.y = *(unsigned*)&o1;
    ((uint2*)g_zh[r])[gw * 32 + lane] = o;
}

// ---------------- fused dual tensor-core GEMM (+ optional pool) --------------
// out = z0 W0 + z1 W1 + (b0+b1), optional relu, fp16 out. Block 128x128,
// 8 warps, warp tile 32x64, mma.sync m16n8k16. If batch != nullptr, also
// stages the tile in smem and accumulates per-graph partial sums (mean pool).
__global__ __launch_bounds__(256) void gemm_dual_mma(
    const __half* __restrict__ WT0, const __half* __restrict__ WT1,
    const float* __restrict__ b0, const float* __restrict__ b1,
    const __half* __restrict__ zh0, const __half* __restrict__ zh1,
    __half* __restrict__ outh, int do_relu, const int* __restrict__ batch)
{
    __shared__ __half SBUF[2 * 128 * 72];   // As | Bs ; reused as h tile for pool
    __half (*As)[72] = (__half(*)[72])SBUF;
    __half (*Bs)[72] = (__half(*)[72])(SBUF + 128 * 72);
    int t = threadIdx.x;
    int warp = t >> 5, lane = t & 31;
    int wm = warp & 3, wn = warp >> 2;
    int g = lane >> 2, tg = lane & 3;
    int row0 = blockIdx.x * 128;

    float acc[2][8][4];
    #pragma unroll
    for (int mt = 0; mt < 2; mt++)
        #pragma unroll
        for (int nt = 0; nt < 8; nt++)
            #pragma unroll
            for (int q = 0; q < 4; q++) acc[mt][nt][q] = 0.f;

    #pragma unroll
    for (int phase = 0; phase < 2; phase++) {
        const __half* Z  = phase ? zh1 : zh0;
        const __half* WT = phase ? WT1 : WT0;
        #pragma unroll
        for (int kc = 0; kc < 128; kc += 64) {
            __syncthreads();
            for (int i = t; i < 128 * 8; i += 256) {
                int row = i >> 3, c8 = (i & 7) * 8;
                uint4 v = make_uint4(0, 0, 0, 0);
                int gr = row0 + row;
                if (gr < NN) v = *(const uint4*)&Z[gr * 128 + kc + c8];
                *(uint4*)&As[row][c8] = v;
            }
            for (int i = t; i < 128 * 8; i += 256) {
                int n = i >> 3, c8 = (i & 7) * 8;
                *(uint4*)&Bs[n][c8] = *(const uint4*)&WT[n * 128 + kc + c8];
            }
            __syncthreads();
            #pragma unroll
            for (int kk = 0; kk < 4; kk++) {
                int k0 = kk * 16;
                unsigned a[2][4];
                #pragma unroll
                for (int mt = 0; mt < 2; mt++) {
                    int rb = wm * 32 + mt * 16;
                    a[mt][0] = *(unsigned*)&As[rb + g][k0 + tg * 2];
                    a[mt][1] = *(unsigned*)&As[rb + g + 8][k0 + tg * 2];
                    a[mt][2] = *(unsigned*)&As[rb + g][k0 + tg * 2 + 8];
                    a[mt][3] = *(unsigned*)&As[rb + g + 8][k0 + tg * 2 + 8];
                }
                #pragma unroll
                for (int nt = 0; nt < 8; nt++) {
                    int cb = wn * 64 + nt * 8 + g;
                    unsigned bf0 = *(unsigned*)&Bs[cb][k0 + tg * 2];
                    unsigned bf1 = *(unsigned*)&Bs[cb][k0 + tg * 2 + 8];
                    #pragma unroll
                    for (int mt = 0; mt < 2; mt++) {
                        asm volatile(
                            "mma.sync.aligned.m16n8k16.row.col.f32.f16.f16.f32 "
                            "{%0,%1,%2,%3}, {%4,%5,%6,%7}, {%8,%9}, {%0,%1,%2,%3};\n"
                            : "+f"(acc[mt][nt][0]), "+f"(acc[mt][nt][1]),
                              "+f"(acc[mt][nt][2]), "+f"(acc[mt][nt][3])
                            : "r"(a[mt][0]), "r"(a[mt][1]), "r"(a[mt][2]), "r"(a[mt][3]),
                              "r"(bf0), "r"(bf1));
                    }
                }
            }
        }
    }
    if (batch) __syncthreads();   // smem reuse: wait for all MMA smem reads

    #pragma unroll
    for (int mt = 0; mt < 2; mt++) {
        int rl = wm * 32 + mt * 16 + g;   // local rows rl, rl+8
        int r_lo = row0 + rl;
        int r_hi = r_lo + 8;
        #pragma unroll
        for (int nt = 0; nt < 8; nt++) {
            int c = wn * 64 + nt * 8 + tg * 2;
            float bia0 = b0[c] + b1[c];
            float bia1 = b0[c + 1] + b1[c + 1];
            float v0 = acc[mt][nt][0] + bia0;
            float v1 = acc[mt][nt][1] + bia1;
            float v2 = acc[mt][nt][2] + bia0;
            float v3 = acc[mt][nt][3] + bia1;
            if (do_relu) {
                v0 = fmaxf(v0, 0.f); v1 = fmaxf(v1, 0.f);
                v2 = fmaxf(v2, 0.f); v3 = fmaxf(v3, 0.f);
            }
            __half2 plo = __floats2half2_rn(v0, v1);
            __half2 phi = __floats2half2_rn(v2, v3);
            if (r_lo < NN) *(__half2*)&outh[r_lo * 128 + c] = plo;
            if (r_hi < NN) *(__half2*)&outh[r_hi * 128 + c] = phi;
            if (batch) {   // stage into smem h-tile (stride 130, pad 2)
                *(__half2*)&SBUF[rl * 130 + c] = plo;
                *(__half2*)&SBUF[(rl + 8) * 130 + c] = phi;
            }
        }
    }
    if (batch) {
        __syncthreads();
        if (t < DD) {
            int row_end = (row0 + 128 > NN) ? (NN - row0) : 128;
            float run = 0.f;
            int cur = __ldg(&batch[row0]);
            for (int rl = 0; rl < row_end; rl++) {
                int gid = __ldg(&batch[row0 + rl]);
                if (gid != cur) {
                    atomicAdd(&g_gsum[cur * DD + t], run);
                    run = 0.f;
                    cur = gid;
                }
                run += __half2float(SBUF[rl * 130 + t]);
            }
            atomicAdd(&g_gsum[cur * DD + t], run);
        }
    }
}

// ---------------- pooling finalize + linear head -----------------------------
__global__ void pool2_kernel(const int* __restrict__ batch,
                             const float* __restrict__ lw, const float* __restrict__ lb,
                             float* __restrict__ out) {
    int g = blockIdx.x;
    int t = threadIdx.x;
    int lo = 0, hi = NN;
    while (lo < hi) { int m = (lo + hi) >> 1; if (batch[m] < g) lo = m + 1; else hi = m; }
    int beg = lo;
    lo = beg; hi = NN;
    while (lo < hi) { int m = (lo + hi) >> 1; if (batch[m] < g + 1) lo = m + 1; else hi = m; }
    int cnt = lo - beg;

    __shared__ float pooled[DD];
    pooled[t] = g_gsum[g * DD + t] / fmaxf((float)cnt, 1.0f);
    __syncthreads();
    if (t < CC) {
        float o = lb[t];
        #pragma unroll 16
        for (int d = 0; d < DD; d++) o = fmaf(pooled[d], lw[d * CC + t], o);
        out[g * CC + t] = o;
    }
}

// ---------------- host launch -------------------------------------------------
extern "C" void kernel_launch(void* const* d_in, const int* in_sizes, int n_in,
                              void* d_out, int out_size)
{
    const float* x     = (const float*)d_in[0];
    const float* W     = (const float*)d_in[1];
    const float* b     = (const float*)d_in[2];
    const float* lin_w = (const float*)d_in[3];
    const float* lin_b = (const float*)d_in[4];
    const int*   ei    = (const int*)d_in[5];
    const int*   batch = (const int*)d_in[6];
    float* out = (float*)d_out;

    __half* d_xh;  cudaGetSymbolAddress((void**)&d_xh, g_xh);
    __half* d_hh;  cudaGetSymbolAddress((void**)&d_hh, g_hh);
    __half* d_zh;  cudaGetSymbolAddress((void**)&d_zh, g_zh);
    __half* d_wt;  cudaGetSymbolAddress((void**)&d_wt, g_WhT);

    // 1. prep: zero deg/gsum, convert x + W
    prep_kernel<<<(NN * DD / 4 + 255) / 256, 256>>>(x, W);
    // 2-5. CSR build
    count_deg_kernel<<<(RR * E4 + 255) / 256, 256>>>(ei);
    bsum_kernel<<<dim3(NBLK, RR), 256>>>();
    write_rowptr_kernel<<<dim3(NBLK, RR), 256>>>();
    fill_csr_kernel<<<(RR * E4 + 255) / 256, 256>>>(ei);

    dim3 agg_grid((NN * 32 + 255) / 256, RR);
    int gemm_grid = (NN + 127) / 128;
    const __half* z0 = d_zh;
    const __half* z1 = d_zh + NN * DD;

    // 6-7. layer 0
    agg_kernel<<<agg_grid, 256>>>(d_xh);
    gemm_dual_mma<<<gemm_grid, 256>>>(d_wt + 0 * DD * DD, d_wt + 1 * DD * DD,
                                      b + 0 * DD, b + 1 * DD, z0, z1, d_hh, 1, nullptr);
    // 8-9. layer 1 (+ fused mean-pool partial sums)
    agg_kernel<<<agg_grid, 256>>>(d_hh);
    gemm_dual_mma<<<gemm_grid, 256>>>(d_wt + 2 * DD * DD, d_wt + 3 * DD * DD,
                                      b + 2 * DD, b + 3 * DD, z0, z1, d_xh, 0, batch);

    // 10. pool finalize + head
    pool2_kernel<<<GG, DD>>>(batch, lin_w, lin_b, out);
}